// round 10
// baseline (speedup 1.0000x reference)
#include <cuda_runtime.h>
#include <cstdint>
#include <cstddef>

#define GF      64
#define EXP_N   8
#define NPTS_MAX 262144

#define TR      128         // rows (points) per tile
#define NTHREADS 256        // 32 row-groups x 8 col-groups
#define RP      68          // A tile row pitch (floats)
#define WP      68          // W tile row pitch (floats)
#define NBLOCKS 296         // 2 per SM on 148-SM sm_100a

// XOR chunk swizzle (proven R9): element (r,k) -> r*RP + ((k/4 ^ s(r))*4) + k%4
#define SROW(r)   (((r) >> 2) & 3)
#define AIDX(r,k) ((r) * RP + ((((k) >> 2) ^ SROW(r)) << 2) + ((k) & 3))
#define A_TILE_FLOATS (TR * RP)

typedef unsigned long long u64;

// ---------------- scratch (no allocations allowed) ----------------
__device__ float g_feat[(size_t)NPTS_MAX * GF];       // gated features [N,64]
__device__ int   g_list[(size_t)EXP_N * NPTS_MAX];    // per-expert point lists
__device__ int   g_cnt[EXP_N];                        // zeroed at end of aux
__device__ int   g_next;                              // expert work queue head (zeroed in aux)

// ---------------- packed f32x2 helpers ----------------
__device__ __forceinline__ u64 fma2(u64 a, u64 b, u64 c)
{
    u64 d;
    asm("fma.rn.f32x2 %0, %1, %2, %3;" : "=l"(d) : "l"(a), "l"(b), "l"(c));
    return d;
}
__device__ __forceinline__ float red2(u64 v, float init)
{
    float lo, hi;
    asm("mov.b64 {%0, %1}, %2;" : "=f"(lo), "=f"(hi) : "l"(v));
    return init + lo + hi;
}

// ---------------- 128x64 GEMM mainloop ----------------
__device__ __forceinline__ void gemm_tile(const float* __restrict__ sA,
                                          const float* __restrict__ sW,
                                          int r0, int colg, u64 acc[4][8])
{
#pragma unroll
    for (int j = 0; j < 4; j++)
#pragma unroll
        for (int i = 0; i < 8; i++) acc[j][i] = 0ULL;

    const int sw = SROW(r0);
    const float* __restrict__ row0 = &sA[(r0 + 0) * RP];
    const float* __restrict__ row1 = &sA[(r0 + 1) * RP];
    const float* __restrict__ row2 = &sA[(r0 + 2) * RP];
    const float* __restrict__ row3 = &sA[(r0 + 3) * RP];

#pragma unroll
    for (int k = 0; k < GF; k += 4) {
        const int co = (((k >> 2) ^ sw) << 2);
        ulonglong2 a0 = *(const ulonglong2*)&row0[co];
        ulonglong2 a1 = *(const ulonglong2*)&row1[co];
        ulonglong2 a2 = *(const ulonglong2*)&row2[co];
        ulonglong2 a3 = *(const ulonglong2*)&row3[co];
#pragma unroll
        for (int i = 0; i < 8; i++) {
            ulonglong2 w = *(const ulonglong2*)&sW[(colg + 8 * i) * WP + k];
            acc[0][i] = fma2(a0.x, w.x, acc[0][i]);
            acc[1][i] = fma2(a1.x, w.x, acc[1][i]);
            acc[2][i] = fma2(a2.x, w.x, acc[2][i]);
            acc[3][i] = fma2(a3.x, w.x, acc[3][i]);
            acc[0][i] = fma2(a0.y, w.y, acc[0][i]);
            acc[1][i] = fma2(a1.y, w.y, acc[1][i]);
            acc[2][i] = fma2(a2.y, w.y, acc[2][i]);
            acc[3][i] = fma2(a3.y, w.y, acc[3][i]);
        }
    }
}

// ---------------- gate smem layout ----------------
#define G_OFF_W    0                          // gw1 [64][WP]
#define G_OFF_A    (G_OFF_W + GF*WP)
#define G_OFF_CRD  (G_OFF_A + A_TILE_FLOATS)
#define G_OFF_FW   (G_OFF_CRD + TR*3)
#define G_OFF_FB   (G_OFF_FW + GF*3)
#define G_OFF_GB1  (G_OFF_FB + GF)
#define G_OFF_LNG  (G_OFF_GB1 + GF)
#define G_OFF_LNB  (G_OFF_LNG + GF)
#define G_OFF_GW2  (G_OFF_LNB + GF)
#define G_OFF_GB2  (G_OFF_GW2 + EXP_N*GF)
#define G_SMEM_FLOATS (G_OFF_GB2 + EXP_N)
#define G_SMEM_BYTES  (G_SMEM_FLOATS * 4)

// ---------------- expert smem layout (3 resident weight tiles) ----------------
#define E_OFF_A    0
#define E_OFF_W3   (E_OFF_A + A_TILE_FLOATS)        // [3][64][WP]
#define E_OFF_SB3  (E_OFF_W3 + 3*GF*WP)             // [3][64]
#define E_OFF_WL   (E_OFF_SB3 + 3*GF)
#define E_OFF_BL   (E_OFF_WL + GF)
#define E_OFF_ID   (E_OFF_BL + 1)                   // int[TR]
#define E_OFF_PRE  (E_OFF_ID + TR)                  // int[9] tile prefix
#define E_OFF_CNT  (E_OFF_PRE + 9)                  // int[8]
#define E_OFF_ITEM (E_OFF_CNT + 8)                  // int[1]
#define E_SMEM_FLOATS (E_OFF_ITEM + 1)
#define E_SMEM_BYTES  (E_SMEM_FLOATS * 4)

// ---------------- gate kernel (persistent) ----------------
__global__ void __launch_bounds__(NTHREADS, 2) gate_kernel(
    const float* __restrict__ coords, const float* __restrict__ fw,
    const float* __restrict__ fb,     const float* __restrict__ gw1,
    const float* __restrict__ gb1,    const float* __restrict__ lng,
    const float* __restrict__ lnb,    const float* __restrict__ gw2,
    const float* __restrict__ gb2,    float* __restrict__ out, int n)
{
    extern __shared__ float dsm[];
    float* sW   = dsm + G_OFF_W;
    float* sA   = dsm + G_OFF_A;
    float* scrd = dsm + G_OFF_CRD;
    float* sfw  = dsm + G_OFF_FW;
    float* sfb  = dsm + G_OFF_FB;
    float* sgb1 = dsm + G_OFF_GB1;
    float* slng = dsm + G_OFF_LNG;
    float* slnb = dsm + G_OFF_LNB;
    float* sgw2 = dsm + G_OFF_GW2;
    float* sgb2 = dsm + G_OFF_GB2;

    const int tid = threadIdx.x;

    // stage all weights/consts ONCE per block
    for (int i = tid; i < GF * GF; i += NTHREADS) {
        int c = i >> 6, k = i & 63;
        sW[c * WP + k] = gw1[i];
    }
    for (int i = tid; i < GF * 3;  i += NTHREADS) sfw[i] = fw[i];
    for (int i = tid; i < GF;      i += NTHREADS) {
        sfb[i]  = fb[i];  sgb1[i] = gb1[i];
        slng[i] = lng[i]; slnb[i] = lnb[i];
    }
    for (int i = tid; i < EXP_N * GF; i += NTHREADS) sgw2[i] = gw2[i];
    if (tid < EXP_N) sgb2[tid] = gb2[tid];

    const int ntiles = (n + TR - 1) / TR;
    const int colg = tid & 7;
    const int r0   = (tid >> 3) * 4;
    const int lane = tid & 31;

    for (int t = blockIdx.x; t < ntiles; t += gridDim.x) {
        const int base = t * TR;
        int nrows = n - base; if (nrows > TR) nrows = TR;

        __syncthreads();   // previous tile's sA/scrd readers done
        for (int i = tid; i < nrows * 3; i += NTHREADS) scrd[i] = coords[(size_t)base * 3 + i];
        if (tid < nrows) out[base + tid] = 0.0f;          // fused init
        __syncthreads();

        // feature = coords @ fw^T + fb, fused g_feat writeback
        for (int i = tid; i < TR * GF; i += NTHREADS) {
            int r = i >> 6, k = i & 63;
            float v = 0.0f;
            if (r < nrows) {
                v = sfb[k] + scrd[3*r]*sfw[3*k] + scrd[3*r+1]*sfw[3*k+1]
                           + scrd[3*r+2]*sfw[3*k+2];
                g_feat[(size_t)base * GF + i] = v;
            }
            sA[AIDX(r, k)] = v;
        }
        __syncthreads();

        u64 acc[4][8];
        gemm_tile(sA, sW, r0, colg, acc);
        __syncthreads();

#pragma unroll
        for (int j = 0; j < 4; j++)
#pragma unroll
            for (int i = 0; i < 8; i++) {
                int c = colg + 8 * i;
                sA[AIDX(r0 + j, c)] = red2(acc[j][i], sgb1[c]);
            }
        __syncthreads();

        const int p = base + tid;
        const bool act = (tid < TR) && (p < n);
        if (act) {
            float a[GF];
            const float* arow = &sA[tid * RP];
            const int sw = SROW(tid);
#pragma unroll
            for (int k = 0; k < GF; k += 4) {
                float4 v = *(const float4*)&arow[(((k >> 2) ^ sw) << 2)];
                a[k+0] = v.x; a[k+1] = v.y; a[k+2] = v.z; a[k+3] = v.w;
            }
            float mu = 0.f;
#pragma unroll
            for (int j = 0; j < GF; j++) mu += a[j];
            mu *= (1.0f / GF);
            float var = 0.f;
#pragma unroll
            for (int j = 0; j < GF; j++) { float d = a[j] - mu; var += d * d; }
            var *= (1.0f / GF);
            const float inv = rsqrtf(var + 1e-5f);
#pragma unroll
            for (int j = 0; j < GF; j++)
                a[j] = (a[j] - mu) * inv * slng[j] + slnb[j];

            float lg[EXP_N];
#pragma unroll
            for (int e = 0; e < EXP_N; e++) {
                float accv = sgb2[e];
#pragma unroll
                for (int j = 0; j < GF; j++) accv += sgw2[e * GF + j] * a[j];
                lg[e] = accv;
            }
            float m1 = -1e30f, m2 = -1e30f;
#pragma unroll
            for (int e = 0; e < EXP_N; e++) {
                float v = lg[e];
                if (v > m1)      { m2 = m1; m1 = v; }
                else if (v > m2) { m2 = v; }
            }
#pragma unroll
            for (int e = 0; e < EXP_N; e++) {
                bool sel = (lg[e] >= m2);
                unsigned bm = __ballot_sync(0xffffffffu, sel);   // warps 0..3 fully active
                if (bm) {
                    int leader = __ffs(bm) - 1;
                    int pos = 0;
                    if (lane == leader) pos = atomicAdd(&g_cnt[e], __popc(bm));
                    pos = __shfl_sync(0xffffffffu, pos, leader);
                    if (sel) {
                        int off = pos + __popc(bm & ((1u << lane) - 1u));
                        g_list[(size_t)e * NPTS_MAX + off] = p;
                    }
                }
            }
        }
    }
}

// ---------------- expert kernel (persistent, work-stealing, 3 resident W tiles) ----------------
__global__ void __launch_bounds__(NTHREADS, 2) expert_kernel(
    const float* __restrict__ we0, const float* __restrict__ be0,
    const float* __restrict__ wm,  const float* __restrict__ bm,
    const float* __restrict__ wl,  const float* __restrict__ bl,
    float* __restrict__ out, int n)
{
    extern __shared__ float dsm[];
    float* sA   = dsm + E_OFF_A;
    float* sW3  = dsm + E_OFF_W3;
    float* sb3  = dsm + E_OFF_SB3;
    float* swl  = dsm + E_OFF_WL;
    float* sbl  = dsm + E_OFF_BL;
    int*   sId  = (int*)(dsm + E_OFF_ID);
    int*   spre = (int*)(dsm + E_OFF_PRE);
    int*   scnt = (int*)(dsm + E_OFF_CNT);
    int*   sitem= (int*)(dsm + E_OFF_ITEM);

    const int tid = threadIdx.x;

    if (tid == 0) {
        int s = 0;
        spre[0] = 0;
#pragma unroll
        for (int e = 0; e < EXP_N; e++) {
            int c = g_cnt[e];
            scnt[e] = c;
            s += (c + TR - 1) / TR;
            spre[e + 1] = s;
        }
    }
    __syncthreads();
    const int total = spre[EXP_N];

    const int colg = tid & 7;
    const int r0   = (tid >> 3) * 4;
    int cur_e = -1;

    while (true) {
        if (tid == 0) sitem[0] = atomicAdd(&g_next, 1);
        __syncthreads();                 // broadcast item; also fences prior tile's sA readers
        const int item = sitem[0];
        if (item >= total) break;

        int e = 0;
        while (item >= spre[e + 1]) e++;
        const int t = item - spre[e];

        if (e != cur_e) {
            cur_e = e;
            // load 3 weight tiles + biases + final-layer weights for this expert
            for (int i = tid; i < 3 * GF * GF; i += NTHREADS) {
                int l = i >> 12, rem = i & 4095;
                int c = rem >> 6, k = rem & 63;
                float v = (l == 0) ? we0[(size_t)e * GF * GF + rem]
                                   : wm[((size_t)(l - 1) * EXP_N + e) * GF * GF + rem];
                sW3[l * GF * WP + c * WP + k] = v;
            }
            if (tid < GF) {
                sb3[tid]          = be0[e * GF + tid];
                sb3[GF + tid]     = bm[((size_t)0 * EXP_N + e) * GF + tid];
                sb3[2 * GF + tid] = bm[((size_t)1 * EXP_N + e) * GF + tid];
                swl[tid]          = wl[e * GF + tid];
            }
            if (tid == 0) sbl[0] = bl[e];
            __syncthreads();
        }

        const int cnt  = scnt[e];
        const int base = t * TR;
        int nrows = cnt - base; if (nrows > TR) nrows = TR;

        for (int i = tid; i < TR; i += NTHREADS)
            sId[i] = (i < nrows) ? g_list[(size_t)e * NPTS_MAX + base + i] : 0;
        __syncthreads();

        for (int i = tid; i < TR * GF; i += NTHREADS) {
            int r = i >> 6, k = i & 63;
            sA[AIDX(r, k)] = (r < nrows) ? g_feat[(size_t)sId[r] * GF + k] : 0.0f;
        }
        __syncthreads();

        const float freq0 = 22.5f + 45.0f * (float)e;   // W0S[e]
#pragma unroll 1
        for (int layer = 0; layer < 3; layer++) {
            const float* sW = sW3 + layer * GF * WP;
            const float* sb = sb3 + layer * GF;
            const float freq = (layer == 0) ? freq0 : 30.0f;

            u64 acc[4][8];
            gemm_tile(sA, sW, r0, colg, acc);
            __syncthreads();                 // everyone done reading sA

#pragma unroll
            for (int j = 0; j < 4; j++)
#pragma unroll
                for (int i = 0; i < 8; i++) {
                    int c = colg + 8 * i;
                    sA[AIDX(r0 + j, c)] = __sinf(freq * red2(acc[j][i], sb[c]));
                }
            __syncthreads();
        }

        if (tid < TR && tid < nrows) {
            float accv = sbl[0];
            const float* arow = &sA[tid * RP];
            const int sw = SROW(tid);
#pragma unroll
            for (int k = 0; k < GF; k += 4) {
                float4 v = *(const float4*)&arow[(((k >> 2) ^ sw) << 2)];
                accv += swl[k]*v.x + swl[k+1]*v.y + swl[k+2]*v.z + swl[k+3]*v.w;
            }
            atomicAdd(&out[sId[tid]], accv);
        }
        // loop-top sync protects sA before next gather
    }
}

__global__ void aux_kernel(float* __restrict__ out, int n, int out_size)
{
    if (threadIdx.x == 0 && blockIdx.x == 0) {
        long long s = 0;
#pragma unroll
        for (int e = 0; e < EXP_N; e++) {
            long long c = (long long)g_cnt[e];
            s += c * c;
        }
        double aux = (double)EXP_N * (double)s / ((double)n * (double)n);
        if (out_size > n) out[n] = (float)aux;
    }
    // reset counters + queue for next graph replay
    if (blockIdx.x == 0 && threadIdx.x < EXP_N) g_cnt[threadIdx.x] = 0;
    if (blockIdx.x == 0 && threadIdx.x == EXP_N) g_next = 0;
}

// ---------------- launcher ----------------
extern "C" void kernel_launch(void* const* d_in, const int* in_sizes, int n_in,
                              void* d_out, int out_size)
{
    const float* coords = (const float*)d_in[0];
    const float* fw   = (const float*)d_in[1];
    const float* fb   = (const float*)d_in[2];
    const float* gw1  = (const float*)d_in[3];
    const float* gb1  = (const float*)d_in[4];
    const float* ln_g = (const float*)d_in[5];
    const float* ln_b = (const float*)d_in[6];
    const float* gw2  = (const float*)d_in[7];
    const float* gb2  = (const float*)d_in[8];
    const float* we0  = (const float*)d_in[9];
    const float* be0  = (const float*)d_in[10];
    const float* wm   = (const float*)d_in[11];
    const float* bm   = (const float*)d_in[12];
    const float* wl   = (const float*)d_in[13];
    const float* bl   = (const float*)d_in[14];
    float* out = (float*)d_out;

    const int n = in_sizes[0] / 3;

    cudaFuncSetAttribute(gate_kernel,   cudaFuncAttributeMaxDynamicSharedMemorySize, G_SMEM_BYTES);
    cudaFuncSetAttribute(expert_kernel, cudaFuncAttributeMaxDynamicSharedMemorySize, E_SMEM_BYTES);

    gate_kernel<<<NBLOCKS, NTHREADS, G_SMEM_BYTES>>>(coords, fw, fb, gw1, gb1,
                                                     ln_g, ln_b, gw2, gb2, out, n);

    expert_kernel<<<NBLOCKS, NTHREADS, E_SMEM_BYTES>>>(we0, be0, wm, bm, wl, bl, out, n);

    aux_kernel<<<1, 32>>>(out, n, out_size);
}

// round 11
// speedup vs baseline: 1.0022x; 1.0022x over previous
#include <cuda_runtime.h>
#include <cstdint>
#include <cstddef>

#define GF      64
#define EXP_N   8
#define NPTS_MAX 262144

#define TR      128         // rows (points) per tile
#define NTHREADS 256        // 32 row-groups x 8 col-groups
#define RP      68          // A tile row pitch (floats)
#define WP      68          // W tile row pitch (floats)
#define NBLOCKS 296         // 2 per SM on 148-SM sm_100a

// XOR chunk swizzle (proven R9): element (r,k) -> r*RP + ((k/4 ^ s(r))*4) + k%4
#define SROW(r)   (((r) >> 2) & 3)
#define AIDX(r,k) ((r) * RP + ((((k) >> 2) ^ SROW(r)) << 2) + ((k) & 3))
#define A_TILE_FLOATS (TR * RP)

typedef unsigned long long u64;

// ---------------- scratch (no allocations allowed) ----------------
__device__ float g_feat[(size_t)NPTS_MAX * GF];       // gated features [N,64]
__device__ int   g_list[(size_t)EXP_N * NPTS_MAX];    // per-expert point lists
__device__ int   g_cnt[EXP_N];                        // zeroed at end of aux
__device__ int   g_next;                              // expert work queue head (zeroed in aux)

// ---------------- packed f32x2 helpers ----------------
__device__ __forceinline__ u64 fma2(u64 a, u64 b, u64 c)
{
    u64 d;
    asm("fma.rn.f32x2 %0, %1, %2, %3;" : "=l"(d) : "l"(a), "l"(b), "l"(c));
    return d;
}
__device__ __forceinline__ float red2(u64 v, float init)
{
    float lo, hi;
    asm("mov.b64 {%0, %1}, %2;" : "=f"(lo), "=f"(hi) : "l"(v));
    return init + lo + hi;
}

// ---------------- 128x64 GEMM mainloop ----------------
__device__ __forceinline__ void gemm_tile(const float* __restrict__ sA,
                                          const float* __restrict__ sW,
                                          int r0, int colg, u64 acc[4][8])
{
#pragma unroll
    for (int j = 0; j < 4; j++)
#pragma unroll
        for (int i = 0; i < 8; i++) acc[j][i] = 0ULL;

    const int sw = SROW(r0);
    const float* __restrict__ row0 = &sA[(r0 + 0) * RP];
    const float* __restrict__ row1 = &sA[(r0 + 1) * RP];
    const float* __restrict__ row2 = &sA[(r0 + 2) * RP];
    const float* __restrict__ row3 = &sA[(r0 + 3) * RP];

#pragma unroll
    for (int k = 0; k < GF; k += 4) {
        const int co = (((k >> 2) ^ sw) << 2);
        ulonglong2 a0 = *(const ulonglong2*)&row0[co];
        ulonglong2 a1 = *(const ulonglong2*)&row1[co];
        ulonglong2 a2 = *(const ulonglong2*)&row2[co];
        ulonglong2 a3 = *(const ulonglong2*)&row3[co];
#pragma unroll
        for (int i = 0; i < 8; i++) {
            ulonglong2 w = *(const ulonglong2*)&sW[(colg + 8 * i) * WP + k];
            acc[0][i] = fma2(a0.x, w.x, acc[0][i]);
            acc[1][i] = fma2(a1.x, w.x, acc[1][i]);
            acc[2][i] = fma2(a2.x, w.x, acc[2][i]);
            acc[3][i] = fma2(a3.x, w.x, acc[3][i]);
            acc[0][i] = fma2(a0.y, w.y, acc[0][i]);
            acc[1][i] = fma2(a1.y, w.y, acc[1][i]);
            acc[2][i] = fma2(a2.y, w.y, acc[2][i]);
            acc[3][i] = fma2(a3.y, w.y, acc[3][i]);
        }
    }
}

// ---------------- gate smem layout ----------------
#define G_OFF_W    0                          // gw1 [64][WP]
#define G_OFF_A    (G_OFF_W + GF*WP)
#define G_OFF_CRD  (G_OFF_A + A_TILE_FLOATS)
#define G_OFF_FW   (G_OFF_CRD + TR*3)
#define G_OFF_FB   (G_OFF_FW + GF*3)
#define G_OFF_GB1  (G_OFF_FB + GF)
#define G_OFF_LNG  (G_OFF_GB1 + GF)
#define G_OFF_LNB  (G_OFF_LNG + GF)
#define G_OFF_GW2  (G_OFF_LNB + GF)
#define G_OFF_GB2  (G_OFF_GW2 + EXP_N*GF)
#define G_SMEM_FLOATS (G_OFF_GB2 + EXP_N)
#define G_SMEM_BYTES  (G_SMEM_FLOATS * 4)

// ---------------- expert smem layout (3 resident weight tiles) ----------------
#define E_OFF_A    0
#define E_OFF_W3   (E_OFF_A + A_TILE_FLOATS)        // [3][64][WP]
#define E_OFF_SB3  (E_OFF_W3 + 3*GF*WP)             // [3][64]
#define E_OFF_WL   (E_OFF_SB3 + 3*GF)
#define E_OFF_BL   (E_OFF_WL + GF)
#define E_OFF_ID   (E_OFF_BL + 1)                   // int[TR]
#define E_OFF_PRE  (E_OFF_ID + TR)                  // int[9] tile prefix
#define E_OFF_CNT  (E_OFF_PRE + 9)                  // int[8]
#define E_OFF_ITEM (E_OFF_CNT + 8)                  // int[1]
#define E_SMEM_FLOATS (E_OFF_ITEM + 1)
#define E_SMEM_BYTES  (E_SMEM_FLOATS * 4)

// ---------------- gate kernel (persistent) ----------------
__global__ void __launch_bounds__(NTHREADS, 2) gate_kernel(
    const float* __restrict__ coords, const float* __restrict__ fw,
    const float* __restrict__ fb,     const float* __restrict__ gw1,
    const float* __restrict__ gb1,    const float* __restrict__ lng,
    const float* __restrict__ lnb,    const float* __restrict__ gw2,
    const float* __restrict__ gb2,    float* __restrict__ out, int n)
{
    extern __shared__ float dsm[];
    float* sW   = dsm + G_OFF_W;
    float* sA   = dsm + G_OFF_A;
    float* scrd = dsm + G_OFF_CRD;
    float* sfw  = dsm + G_OFF_FW;
    float* sfb  = dsm + G_OFF_FB;
    float* sgb1 = dsm + G_OFF_GB1;
    float* slng = dsm + G_OFF_LNG;
    float* slnb = dsm + G_OFF_LNB;
    float* sgw2 = dsm + G_OFF_GW2;
    float* sgb2 = dsm + G_OFF_GB2;

    const int tid = threadIdx.x;

    // stage all weights/consts ONCE per block
    for (int i = tid; i < GF * GF; i += NTHREADS) {
        int c = i >> 6, k = i & 63;
        sW[c * WP + k] = gw1[i];
    }
    for (int i = tid; i < GF * 3;  i += NTHREADS) sfw[i] = fw[i];
    for (int i = tid; i < GF;      i += NTHREADS) {
        sfb[i]  = fb[i];  sgb1[i] = gb1[i];
        slng[i] = lng[i]; slnb[i] = lnb[i];
    }
    for (int i = tid; i < EXP_N * GF; i += NTHREADS) sgw2[i] = gw2[i];
    if (tid < EXP_N) sgb2[tid] = gb2[tid];

    const int ntiles = (n + TR - 1) / TR;
    const int colg = tid & 7;
    const int r0   = (tid >> 3) * 4;
    const int lane = tid & 31;

    for (int t = blockIdx.x; t < ntiles; t += gridDim.x) {
        const int base = t * TR;
        int nrows = n - base; if (nrows > TR) nrows = TR;

        __syncthreads();   // previous tile's sA/scrd readers done
        for (int i = tid; i < nrows * 3; i += NTHREADS) scrd[i] = coords[(size_t)base * 3 + i];
        if (tid < nrows) out[base + tid] = 0.0f;          // fused init
        __syncthreads();

        // feature = coords @ fw^T + fb, fused g_feat writeback
        for (int i = tid; i < TR * GF; i += NTHREADS) {
            int r = i >> 6, k = i & 63;
            float v = 0.0f;
            if (r < nrows) {
                v = sfb[k] + scrd[3*r]*sfw[3*k] + scrd[3*r+1]*sfw[3*k+1]
                           + scrd[3*r+2]*sfw[3*k+2];
                g_feat[(size_t)base * GF + i] = v;
            }
            sA[AIDX(r, k)] = v;
        }
        __syncthreads();

        u64 acc[4][8];
        gemm_tile(sA, sW, r0, colg, acc);
        __syncthreads();

#pragma unroll
        for (int j = 0; j < 4; j++)
#pragma unroll
            for (int i = 0; i < 8; i++) {
                int c = colg + 8 * i;
                sA[AIDX(r0 + j, c)] = red2(acc[j][i], sgb1[c]);
            }
        __syncthreads();

        const int p = base + tid;
        const bool act = (tid < TR) && (p < n);
        if (act) {
            float a[GF];
            const float* arow = &sA[tid * RP];
            const int sw = SROW(tid);
#pragma unroll
            for (int k = 0; k < GF; k += 4) {
                float4 v = *(const float4*)&arow[(((k >> 2) ^ sw) << 2)];
                a[k+0] = v.x; a[k+1] = v.y; a[k+2] = v.z; a[k+3] = v.w;
            }
            float mu = 0.f;
#pragma unroll
            for (int j = 0; j < GF; j++) mu += a[j];
            mu *= (1.0f / GF);
            float var = 0.f;
#pragma unroll
            for (int j = 0; j < GF; j++) { float d = a[j] - mu; var += d * d; }
            var *= (1.0f / GF);
            const float inv = rsqrtf(var + 1e-5f);
#pragma unroll
            for (int j = 0; j < GF; j++)
                a[j] = (a[j] - mu) * inv * slng[j] + slnb[j];

            float lg[EXP_N];
#pragma unroll
            for (int e = 0; e < EXP_N; e++) {
                float accv = sgb2[e];
#pragma unroll
                for (int j = 0; j < GF; j++) accv += sgw2[e * GF + j] * a[j];
                lg[e] = accv;
            }
            float m1 = -1e30f, m2 = -1e30f;
#pragma unroll
            for (int e = 0; e < EXP_N; e++) {
                float v = lg[e];
                if (v > m1)      { m2 = m1; m1 = v; }
                else if (v > m2) { m2 = v; }
            }
#pragma unroll
            for (int e = 0; e < EXP_N; e++) {
                bool sel = (lg[e] >= m2);
                unsigned bm = __ballot_sync(0xffffffffu, sel);   // warps 0..3 fully active
                if (bm) {
                    int leader = __ffs(bm) - 1;
                    int pos = 0;
                    if (lane == leader) pos = atomicAdd(&g_cnt[e], __popc(bm));
                    pos = __shfl_sync(0xffffffffu, pos, leader);
                    if (sel) {
                        int off = pos + __popc(bm & ((1u << lane) - 1u));
                        g_list[(size_t)e * NPTS_MAX + off] = p;
                    }
                }
            }
        }
    }
}

// ---------------- expert kernel (persistent, work-stealing, 3 resident W tiles) ----------------
__global__ void __launch_bounds__(NTHREADS, 2) expert_kernel(
    const float* __restrict__ we0, const float* __restrict__ be0,
    const float* __restrict__ wm,  const float* __restrict__ bm,
    const float* __restrict__ wl,  const float* __restrict__ bl,
    float* __restrict__ out, int n)
{
    extern __shared__ float dsm[];
    float* sA   = dsm + E_OFF_A;
    float* sW3  = dsm + E_OFF_W3;
    float* sb3  = dsm + E_OFF_SB3;
    float* swl  = dsm + E_OFF_WL;
    float* sbl  = dsm + E_OFF_BL;
    int*   sId  = (int*)(dsm + E_OFF_ID);
    int*   spre = (int*)(dsm + E_OFF_PRE);
    int*   scnt = (int*)(dsm + E_OFF_CNT);
    int*   sitem= (int*)(dsm + E_OFF_ITEM);

    const int tid = threadIdx.x;

    if (tid == 0) {
        int s = 0;
        spre[0] = 0;
#pragma unroll
        for (int e = 0; e < EXP_N; e++) {
            int c = g_cnt[e];
            scnt[e] = c;
            s += (c + TR - 1) / TR;
            spre[e + 1] = s;
        }
    }
    __syncthreads();
    const int total = spre[EXP_N];

    const int colg = tid & 7;
    const int r0   = (tid >> 3) * 4;
    int cur_e = -1;

    while (true) {
        if (tid == 0) sitem[0] = atomicAdd(&g_next, 1);
        __syncthreads();                 // broadcast item; also fences prior tile's sA readers
        const int item = sitem[0];
        if (item >= total) break;

        int e = 0;
        while (item >= spre[e + 1]) e++;
        const int t = item - spre[e];

        if (e != cur_e) {
            cur_e = e;
            // load 3 weight tiles + biases + final-layer weights for this expert
            for (int i = tid; i < 3 * GF * GF; i += NTHREADS) {
                int l = i >> 12, rem = i & 4095;
                int c = rem >> 6, k = rem & 63;
                float v = (l == 0) ? we0[(size_t)e * GF * GF + rem]
                                   : wm[((size_t)(l - 1) * EXP_N + e) * GF * GF + rem];
                sW3[l * GF * WP + c * WP + k] = v;
            }
            if (tid < GF) {
                sb3[tid]          = be0[e * GF + tid];
                sb3[GF + tid]     = bm[((size_t)0 * EXP_N + e) * GF + tid];
                sb3[2 * GF + tid] = bm[((size_t)1 * EXP_N + e) * GF + tid];
                swl[tid]          = wl[e * GF + tid];
            }
            if (tid == 0) sbl[0] = bl[e];
            __syncthreads();
        }

        const int cnt  = scnt[e];
        const int base = t * TR;
        int nrows = cnt - base; if (nrows > TR) nrows = TR;

        for (int i = tid; i < TR; i += NTHREADS)
            sId[i] = (i < nrows) ? g_list[(size_t)e * NPTS_MAX + base + i] : 0;
        __syncthreads();

        for (int i = tid; i < TR * GF; i += NTHREADS) {
            int r = i >> 6, k = i & 63;
            sA[AIDX(r, k)] = (r < nrows) ? g_feat[(size_t)sId[r] * GF + k] : 0.0f;
        }
        __syncthreads();

        const float freq0 = 22.5f + 45.0f * (float)e;   // W0S[e]
#pragma unroll 1
        for (int layer = 0; layer < 3; layer++) {
            const float* sW = sW3 + layer * GF * WP;
            const float* sb = sb3 + layer * GF;
            const float freq = (layer == 0) ? freq0 : 30.0f;

            u64 acc[4][8];
            gemm_tile(sA, sW, r0, colg, acc);
            __syncthreads();                 // everyone done reading sA

#pragma unroll
            for (int j = 0; j < 4; j++)
#pragma unroll
                for (int i = 0; i < 8; i++) {
                    int c = colg + 8 * i;
                    sA[AIDX(r0 + j, c)] = __sinf(freq * red2(acc[j][i], sb[c]));
                }
            __syncthreads();
        }

        if (tid < TR && tid < nrows) {
            float accv = sbl[0];
            const float* arow = &sA[tid * RP];
            const int sw = SROW(tid);
#pragma unroll
            for (int k = 0; k < GF; k += 4) {
                float4 v = *(const float4*)&arow[(((k >> 2) ^ sw) << 2)];
                accv += swl[k]*v.x + swl[k+1]*v.y + swl[k+2]*v.z + swl[k+3]*v.w;
            }
            atomicAdd(&out[sId[tid]], accv);
        }
        // loop-top sync protects sA before next gather
    }
}

__global__ void aux_kernel(float* __restrict__ out, int n, int out_size)
{
    if (threadIdx.x == 0 && blockIdx.x == 0) {
        long long s = 0;
#pragma unroll
        for (int e = 0; e < EXP_N; e++) {
            long long c = (long long)g_cnt[e];
            s += c * c;
        }
        double aux = (double)EXP_N * (double)s / ((double)n * (double)n);
        if (out_size > n) out[n] = (float)aux;
    }
    // reset counters + queue for next graph replay
    if (blockIdx.x == 0 && threadIdx.x < EXP_N) g_cnt[threadIdx.x] = 0;
    if (blockIdx.x == 0 && threadIdx.x == EXP_N) g_next = 0;
}

// ---------------- launcher ----------------
extern "C" void kernel_launch(void* const* d_in, const int* in_sizes, int n_in,
                              void* d_out, int out_size)
{
    const float* coords = (const float*)d_in[0];
    const float* fw   = (const float*)d_in[1];
    const float* fb   = (const float*)d_in[2];
    const float* gw1  = (const float*)d_in[3];
    const float* gb1  = (const float*)d_in[4];
    const float* ln_g = (const float*)d_in[5];
    const float* ln_b = (const float*)d_in[6];
    const float* gw2  = (const float*)d_in[7];
    const float* gb2  = (const float*)d_in[8];
    const float* we0  = (const float*)d_in[9];
    const float* be0  = (const float*)d_in[10];
    const float* wm   = (const float*)d_in[11];
    const float* bm   = (const float*)d_in[12];
    const float* wl   = (const float*)d_in[13];
    const float* bl   = (const float*)d_in[14];
    float* out = (float*)d_out;

    const int n = in_sizes[0] / 3;

    cudaFuncSetAttribute(gate_kernel,   cudaFuncAttributeMaxDynamicSharedMemorySize, G_SMEM_BYTES);
    cudaFuncSetAttribute(expert_kernel, cudaFuncAttributeMaxDynamicSharedMemorySize, E_SMEM_BYTES);

    gate_kernel<<<NBLOCKS, NTHREADS, G_SMEM_BYTES>>>(coords, fw, fb, gw1, gb1,
                                                     ln_g, ln_b, gw2, gb2, out, n);

    expert_kernel<<<NBLOCKS, NTHREADS, E_SMEM_BYTES>>>(we0, be0, wm, bm, wl, bl, out, n);

    aux_kernel<<<1, 32>>>(out, n, out_size);
}

// round 12
// speedup vs baseline: 1.0028x; 1.0006x over previous
#include <cuda_runtime.h>
#include <cstdint>
#include <cstddef>

#define GF      64
#define EXP_N   8
#define NPTS_MAX 262144

#define TR      128         // rows (points) per tile
#define NTHREADS 256        // 32 row-groups x 8 col-groups
#define RP      68          // A tile row pitch (floats)
#define WP      68          // W tile row pitch (floats)
#define NBLOCKS 296         // 2 per SM on 148-SM sm_100a

// XOR chunk swizzle (proven R9): element (r,k) -> r*RP + ((k/4 ^ s(r))*4) + k%4
#define SROW(r)   (((r) >> 2) & 3)
#define AIDX(r,k) ((r) * RP + ((((k) >> 2) ^ SROW(r)) << 2) + ((k) & 3))
#define A_TILE_FLOATS (TR * RP)

typedef unsigned long long u64;

// ---------------- scratch (no allocations allowed) ----------------
__device__ float g_feat[(size_t)NPTS_MAX * GF];       // gated features [N,64]
__device__ int   g_list[(size_t)EXP_N * NPTS_MAX];    // per-expert point lists
__device__ int   g_cnt[EXP_N];                        // zeroed at end of aux
__device__ int   g_next;                              // expert work queue head (zeroed in aux)

// ---------------- packed f32x2 helpers ----------------
__device__ __forceinline__ u64 fma2(u64 a, u64 b, u64 c)
{
    u64 d;
    asm("fma.rn.f32x2 %0, %1, %2, %3;" : "=l"(d) : "l"(a), "l"(b), "l"(c));
    return d;
}
__device__ __forceinline__ float red2(u64 v, float init)
{
    float lo, hi;
    asm("mov.b64 {%0, %1}, %2;" : "=f"(lo), "=f"(hi) : "l"(v));
    return init + lo + hi;
}

// ---------------- 128x64 GEMM mainloop ----------------
__device__ __forceinline__ void gemm_tile(const float* __restrict__ sA,
                                          const float* __restrict__ sW,
                                          int r0, int colg, u64 acc[4][8])
{
#pragma unroll
    for (int j = 0; j < 4; j++)
#pragma unroll
        for (int i = 0; i < 8; i++) acc[j][i] = 0ULL;

    const int sw = SROW(r0);
    const float* __restrict__ row0 = &sA[(r0 + 0) * RP];
    const float* __restrict__ row1 = &sA[(r0 + 1) * RP];
    const float* __restrict__ row2 = &sA[(r0 + 2) * RP];
    const float* __restrict__ row3 = &sA[(r0 + 3) * RP];

#pragma unroll
    for (int k = 0; k < GF; k += 4) {
        const int co = (((k >> 2) ^ sw) << 2);
        ulonglong2 a0 = *(const ulonglong2*)&row0[co];
        ulonglong2 a1 = *(const ulonglong2*)&row1[co];
        ulonglong2 a2 = *(const ulonglong2*)&row2[co];
        ulonglong2 a3 = *(const ulonglong2*)&row3[co];
#pragma unroll
        for (int i = 0; i < 8; i++) {
            ulonglong2 w = *(const ulonglong2*)&sW[(colg + 8 * i) * WP + k];
            acc[0][i] = fma2(a0.x, w.x, acc[0][i]);
            acc[1][i] = fma2(a1.x, w.x, acc[1][i]);
            acc[2][i] = fma2(a2.x, w.x, acc[2][i]);
            acc[3][i] = fma2(a3.x, w.x, acc[3][i]);
            acc[0][i] = fma2(a0.y, w.y, acc[0][i]);
            acc[1][i] = fma2(a1.y, w.y, acc[1][i]);
            acc[2][i] = fma2(a2.y, w.y, acc[2][i]);
            acc[3][i] = fma2(a3.y, w.y, acc[3][i]);
        }
    }
}

// ---------------- gate smem layout ----------------
#define G_OFF_W    0                          // gw1 [64][WP]
#define G_OFF_A    (G_OFF_W + GF*WP)
#define G_OFF_CRD  (G_OFF_A + A_TILE_FLOATS)
#define G_OFF_FW   (G_OFF_CRD + TR*3)
#define G_OFF_FB   (G_OFF_FW + GF*3)
#define G_OFF_GB1  (G_OFF_FB + GF)
#define G_OFF_LNG  (G_OFF_GB1 + GF)
#define G_OFF_LNB  (G_OFF_LNG + GF)
#define G_OFF_GW2  (G_OFF_LNB + GF)
#define G_OFF_GB2  (G_OFF_GW2 + EXP_N*GF)
#define G_SMEM_FLOATS (G_OFF_GB2 + EXP_N)
#define G_SMEM_BYTES  (G_SMEM_FLOATS * 4)

// ---------------- expert smem layout (3 resident weight tiles) ----------------
#define E_OFF_A    0
#define E_OFF_W3   (E_OFF_A + A_TILE_FLOATS)        // [3][64][WP]
#define E_OFF_SB3  (E_OFF_W3 + 3*GF*WP)             // [3][64]
#define E_OFF_WL   (E_OFF_SB3 + 3*GF)
#define E_OFF_BL   (E_OFF_WL + GF)
#define E_OFF_ID   (E_OFF_BL + 1)                   // int[TR]
#define E_OFF_PRE  (E_OFF_ID + TR)                  // int[9] tile prefix
#define E_OFF_CNT  (E_OFF_PRE + 9)                  // int[8]
#define E_OFF_ITEM (E_OFF_CNT + 8)                  // int[1]
#define E_SMEM_FLOATS (E_OFF_ITEM + 1)
#define E_SMEM_BYTES  (E_SMEM_FLOATS * 4)

// ---------------- gate kernel (persistent) ----------------
__global__ void __launch_bounds__(NTHREADS, 2) gate_kernel(
    const float* __restrict__ coords, const float* __restrict__ fw,
    const float* __restrict__ fb,     const float* __restrict__ gw1,
    const float* __restrict__ gb1,    const float* __restrict__ lng,
    const float* __restrict__ lnb,    const float* __restrict__ gw2,
    const float* __restrict__ gb2,    float* __restrict__ out, int n)
{
    extern __shared__ float dsm[];
    float* sW   = dsm + G_OFF_W;
    float* sA   = dsm + G_OFF_A;
    float* scrd = dsm + G_OFF_CRD;
    float* sfw  = dsm + G_OFF_FW;
    float* sfb  = dsm + G_OFF_FB;
    float* sgb1 = dsm + G_OFF_GB1;
    float* slng = dsm + G_OFF_LNG;
    float* slnb = dsm + G_OFF_LNB;
    float* sgw2 = dsm + G_OFF_GW2;
    float* sgb2 = dsm + G_OFF_GB2;

    const int tid = threadIdx.x;

    // stage all weights/consts ONCE per block
    for (int i = tid; i < GF * GF; i += NTHREADS) {
        int c = i >> 6, k = i & 63;
        sW[c * WP + k] = gw1[i];
    }
    for (int i = tid; i < GF * 3;  i += NTHREADS) sfw[i] = fw[i];
    for (int i = tid; i < GF;      i += NTHREADS) {
        sfb[i]  = fb[i];  sgb1[i] = gb1[i];
        slng[i] = lng[i]; slnb[i] = lnb[i];
    }
    for (int i = tid; i < EXP_N * GF; i += NTHREADS) sgw2[i] = gw2[i];
    if (tid < EXP_N) sgb2[tid] = gb2[tid];

    const int ntiles = (n + TR - 1) / TR;
    const int colg = tid & 7;
    const int r0   = (tid >> 3) * 4;
    const int lane = tid & 31;

    for (int t = blockIdx.x; t < ntiles; t += gridDim.x) {
        const int base = t * TR;
        int nrows = n - base; if (nrows > TR) nrows = TR;

        __syncthreads();   // previous tile's sA/scrd readers done
        for (int i = tid; i < nrows * 3; i += NTHREADS) scrd[i] = coords[(size_t)base * 3 + i];
        if (tid < nrows) out[base + tid] = 0.0f;          // fused init
        __syncthreads();

        // feature = coords @ fw^T + fb, fused g_feat writeback
        for (int i = tid; i < TR * GF; i += NTHREADS) {
            int r = i >> 6, k = i & 63;
            float v = 0.0f;
            if (r < nrows) {
                v = sfb[k] + scrd[3*r]*sfw[3*k] + scrd[3*r+1]*sfw[3*k+1]
                           + scrd[3*r+2]*sfw[3*k+2];
                g_feat[(size_t)base * GF + i] = v;
            }
            sA[AIDX(r, k)] = v;
        }
        __syncthreads();

        u64 acc[4][8];
        gemm_tile(sA, sW, r0, colg, acc);
        __syncthreads();

#pragma unroll
        for (int j = 0; j < 4; j++)
#pragma unroll
            for (int i = 0; i < 8; i++) {
                int c = colg + 8 * i;
                sA[AIDX(r0 + j, c)] = red2(acc[j][i], sgb1[c]);
            }
        __syncthreads();

        const int p = base + tid;
        const bool act = (tid < TR) && (p < n);
        if (act) {
            float a[GF];
            const float* arow = &sA[tid * RP];
            const int sw = SROW(tid);
#pragma unroll
            for (int k = 0; k < GF; k += 4) {
                float4 v = *(const float4*)&arow[(((k >> 2) ^ sw) << 2)];
                a[k+0] = v.x; a[k+1] = v.y; a[k+2] = v.z; a[k+3] = v.w;
            }
            float mu = 0.f;
#pragma unroll
            for (int j = 0; j < GF; j++) mu += a[j];
            mu *= (1.0f / GF);
            float var = 0.f;
#pragma unroll
            for (int j = 0; j < GF; j++) { float d = a[j] - mu; var += d * d; }
            var *= (1.0f / GF);
            const float inv = rsqrtf(var + 1e-5f);
#pragma unroll
            for (int j = 0; j < GF; j++)
                a[j] = (a[j] - mu) * inv * slng[j] + slnb[j];

            float lg[EXP_N];
#pragma unroll
            for (int e = 0; e < EXP_N; e++) {
                float accv = sgb2[e];
#pragma unroll
                for (int j = 0; j < GF; j++) accv += sgw2[e * GF + j] * a[j];
                lg[e] = accv;
            }
            float m1 = -1e30f, m2 = -1e30f;
#pragma unroll
            for (int e = 0; e < EXP_N; e++) {
                float v = lg[e];
                if (v > m1)      { m2 = m1; m1 = v; }
                else if (v > m2) { m2 = v; }
            }
#pragma unroll
            for (int e = 0; e < EXP_N; e++) {
                bool sel = (lg[e] >= m2);
                unsigned bm = __ballot_sync(0xffffffffu, sel);   // warps 0..3 fully active
                if (bm) {
                    int leader = __ffs(bm) - 1;
                    int pos = 0;
                    if (lane == leader) pos = atomicAdd(&g_cnt[e], __popc(bm));
                    pos = __shfl_sync(0xffffffffu, pos, leader);
                    if (sel) {
                        int off = pos + __popc(bm & ((1u << lane) - 1u));
                        g_list[(size_t)e * NPTS_MAX + off] = p;
                    }
                }
            }
        }
    }
}

// ---------------- expert kernel (persistent, work-stealing, 3 resident W tiles) ----------------
__global__ void __launch_bounds__(NTHREADS, 2) expert_kernel(
    const float* __restrict__ we0, const float* __restrict__ be0,
    const float* __restrict__ wm,  const float* __restrict__ bm,
    const float* __restrict__ wl,  const float* __restrict__ bl,
    float* __restrict__ out, int n)
{
    extern __shared__ float dsm[];
    float* sA   = dsm + E_OFF_A;
    float* sW3  = dsm + E_OFF_W3;
    float* sb3  = dsm + E_OFF_SB3;
    float* swl  = dsm + E_OFF_WL;
    float* sbl  = dsm + E_OFF_BL;
    int*   sId  = (int*)(dsm + E_OFF_ID);
    int*   spre = (int*)(dsm + E_OFF_PRE);
    int*   scnt = (int*)(dsm + E_OFF_CNT);
    int*   sitem= (int*)(dsm + E_OFF_ITEM);

    const int tid = threadIdx.x;

    if (tid == 0) {
        int s = 0;
        spre[0] = 0;
#pragma unroll
        for (int e = 0; e < EXP_N; e++) {
            int c = g_cnt[e];
            scnt[e] = c;
            s += (c + TR - 1) / TR;
            spre[e + 1] = s;
        }
    }
    __syncthreads();
    const int total = spre[EXP_N];

    const int colg = tid & 7;
    const int r0   = (tid >> 3) * 4;
    int cur_e = -1;

    while (true) {
        if (tid == 0) sitem[0] = atomicAdd(&g_next, 1);
        __syncthreads();                 // broadcast item; also fences prior tile's sA readers
        const int item = sitem[0];
        if (item >= total) break;

        int e = 0;
        while (item >= spre[e + 1]) e++;
        const int t = item - spre[e];

        if (e != cur_e) {
            cur_e = e;
            // load 3 weight tiles + biases + final-layer weights for this expert
            for (int i = tid; i < 3 * GF * GF; i += NTHREADS) {
                int l = i >> 12, rem = i & 4095;
                int c = rem >> 6, k = rem & 63;
                float v = (l == 0) ? we0[(size_t)e * GF * GF + rem]
                                   : wm[((size_t)(l - 1) * EXP_N + e) * GF * GF + rem];
                sW3[l * GF * WP + c * WP + k] = v;
            }
            if (tid < GF) {
                sb3[tid]          = be0[e * GF + tid];
                sb3[GF + tid]     = bm[((size_t)0 * EXP_N + e) * GF + tid];
                sb3[2 * GF + tid] = bm[((size_t)1 * EXP_N + e) * GF + tid];
                swl[tid]          = wl[e * GF + tid];
            }
            if (tid == 0) sbl[0] = bl[e];
            __syncthreads();
        }

        const int cnt  = scnt[e];
        const int base = t * TR;
        int nrows = cnt - base; if (nrows > TR) nrows = TR;

        for (int i = tid; i < TR; i += NTHREADS)
            sId[i] = (i < nrows) ? g_list[(size_t)e * NPTS_MAX + base + i] : 0;
        __syncthreads();

        for (int i = tid; i < TR * GF; i += NTHREADS) {
            int r = i >> 6, k = i & 63;
            sA[AIDX(r, k)] = (r < nrows) ? g_feat[(size_t)sId[r] * GF + k] : 0.0f;
        }
        __syncthreads();

        const float freq0 = 22.5f + 45.0f * (float)e;   // W0S[e]
#pragma unroll 1
        for (int layer = 0; layer < 3; layer++) {
            const float* sW = sW3 + layer * GF * WP;
            const float* sb = sb3 + layer * GF;
            const float freq = (layer == 0) ? freq0 : 30.0f;

            u64 acc[4][8];
            gemm_tile(sA, sW, r0, colg, acc);
            __syncthreads();                 // everyone done reading sA

#pragma unroll
            for (int j = 0; j < 4; j++)
#pragma unroll
                for (int i = 0; i < 8; i++) {
                    int c = colg + 8 * i;
                    sA[AIDX(r0 + j, c)] = __sinf(freq * red2(acc[j][i], sb[c]));
                }
            __syncthreads();
        }

        if (tid < TR && tid < nrows) {
            float accv = sbl[0];
            const float* arow = &sA[tid * RP];
            const int sw = SROW(tid);
#pragma unroll
            for (int k = 0; k < GF; k += 4) {
                float4 v = *(const float4*)&arow[(((k >> 2) ^ sw) << 2)];
                accv += swl[k]*v.x + swl[k+1]*v.y + swl[k+2]*v.z + swl[k+3]*v.w;
            }
            atomicAdd(&out[sId[tid]], accv);
        }
        // loop-top sync protects sA before next gather
    }
}

__global__ void aux_kernel(float* __restrict__ out, int n, int out_size)
{
    if (threadIdx.x == 0 && blockIdx.x == 0) {
        long long s = 0;
#pragma unroll
        for (int e = 0; e < EXP_N; e++) {
            long long c = (long long)g_cnt[e];
            s += c * c;
        }
        double aux = (double)EXP_N * (double)s / ((double)n * (double)n);
        if (out_size > n) out[n] = (float)aux;
    }
    // reset counters + queue for next graph replay
    if (blockIdx.x == 0 && threadIdx.x < EXP_N) g_cnt[threadIdx.x] = 0;
    if (blockIdx.x == 0 && threadIdx.x == EXP_N) g_next = 0;
}

// ---------------- launcher ----------------
extern "C" void kernel_launch(void* const* d_in, const int* in_sizes, int n_in,
                              void* d_out, int out_size)
{
    const float* coords = (const float*)d_in[0];
    const float* fw   = (const float*)d_in[1];
    const float* fb   = (const float*)d_in[2];
    const float* gw1  = (const float*)d_in[3];
    const float* gb1  = (const float*)d_in[4];
    const float* ln_g = (const float*)d_in[5];
    const float* ln_b = (const float*)d_in[6];
    const float* gw2  = (const float*)d_in[7];
    const float* gb2  = (const float*)d_in[8];
    const float* we0  = (const float*)d_in[9];
    const float* be0  = (const float*)d_in[10];
    const float* wm   = (const float*)d_in[11];
    const float* bm   = (const float*)d_in[12];
    const float* wl   = (const float*)d_in[13];
    const float* bl   = (const float*)d_in[14];
    float* out = (float*)d_out;

    const int n = in_sizes[0] / 3;

    cudaFuncSetAttribute(gate_kernel,   cudaFuncAttributeMaxDynamicSharedMemorySize, G_SMEM_BYTES);
    cudaFuncSetAttribute(expert_kernel, cudaFuncAttributeMaxDynamicSharedMemorySize, E_SMEM_BYTES);

    gate_kernel<<<NBLOCKS, NTHREADS, G_SMEM_BYTES>>>(coords, fw, fb, gw1, gb1,
                                                     ln_g, ln_b, gw2, gb2, out, n);

    expert_kernel<<<NBLOCKS, NTHREADS, E_SMEM_BYTES>>>(we0, be0, wm, bm, wl, bl, out, n);

    aux_kernel<<<1, 32>>>(out, n, out_size);
}